// round 2
// baseline (speedup 1.0000x reference)
#include <cuda_runtime.h>

#define NN 50000
#define NE 800000
#define NG 512
#define HID 128
#define EIN 64

// Scratch (device globals: allocation-free rule)
__device__ float g_bufA[NN * HID];   // aggr / MLP input
__device__ float g_bufB[NN * HID];   // MLP hidden
__device__ float g_bufC[NN * HID];   // layer output
__device__ float g_pool[NG * HID];   // pooled per-graph features

// ---------------------------------------------------------------------------
__global__ void copy_kernel(const float4* __restrict__ s, float4* __restrict__ d, int n) {
    int i = blockIdx.x * blockDim.x + threadIdx.x;
    int stride = gridDim.x * blockDim.x;
    for (; i < n; i += stride) d[i] = s[i];
}

// ---------------------------------------------------------------------------
// Fused edge kernel: aggr[dst] += relu(x[src] + attr @ W + b)
// aggr must be pre-initialized with the residual (x), giving hpre = x + sum(m).
// Warp processes 8 edges at a time; lane owns columns [lane*4, lane*4+4).
__global__ void edge_kernel(const float* __restrict__ xin,
                            const float* __restrict__ eattr,
                            const int* __restrict__ ei,         // [2, NE] int32
                            const float* __restrict__ W,        // [64,128]
                            const float* __restrict__ bias,     // [128]
                            float* __restrict__ aggr) {
    extern __shared__ float sh[];
    float* sW = sh;                     // 64*128 = 8192 floats
    float* sattr = sh + EIN * HID;      // 8 warps * 8 edges * 64 = 4096 floats
    int tid = threadIdx.x;
    for (int i = tid; i < EIN * HID; i += blockDim.x) sW[i] = W[i];
    __syncthreads();

    int warp = tid >> 5, lane = tid & 31;
    float4 bb = *(const float4*)(bias + lane * 4);
    float* sat = sattr + warp * (8 * EIN);

    int gw = blockIdx.x * 8 + warp;
    int nw = gridDim.x * 8;
    const int* src = ei;
    const int* dst = ei + NE;

    for (int base = gw * 8; base < NE; base += nw * 8) {
        __syncwarp();
        #pragma unroll
        for (int e = 0; e < 8; e++) {
            int eid = base + e;
            if (eid < NE) {
                const float* ap = eattr + (size_t)eid * EIN;
                sat[e * EIN + lane]      = ap[lane];
                sat[e * EIN + lane + 32] = ap[lane + 32];
            }
        }
        __syncwarp();

        float4 acc[8];
        #pragma unroll
        for (int e = 0; e < 8; e++) acc[e] = bb;

        #pragma unroll 4
        for (int k = 0; k < EIN; k++) {
            float4 wv = *(const float4*)&sW[k * HID + lane * 4];
            #pragma unroll
            for (int e = 0; e < 8; e++) {
                float a = sat[e * EIN + k];
                acc[e].x = fmaf(a, wv.x, acc[e].x);
                acc[e].y = fmaf(a, wv.y, acc[e].y);
                acc[e].z = fmaf(a, wv.z, acc[e].z);
                acc[e].w = fmaf(a, wv.w, acc[e].w);
            }
        }

        #pragma unroll
        for (int e = 0; e < 8; e++) {
            int eid = base + e;
            if (eid >= NE) break;
            int sI = src[eid], dI = dst[eid];
            float4 xv = *(const float4*)(xin + (size_t)sI * HID + lane * 4);
            float4 m;
            m.x = fmaxf(xv.x + acc[e].x, 0.f);
            m.y = fmaxf(xv.y + acc[e].y, 0.f);
            m.z = fmaxf(xv.z + acc[e].z, 0.f);
            m.w = fmaxf(xv.w + acc[e].w, 0.f);
            atomicAdd((float4*)(aggr + (size_t)dI * HID + lane * 4), m);
        }
    }
}

// ---------------------------------------------------------------------------
// C[M,128] = act(A[M,128] @ W[128,128] + bias), optional relu.
// Block tile 64x128, 256 threads, micro-tile 8 rows x 4 cols, K chunked by 32.
__global__ void gemm128_kernel(const float* __restrict__ A,
                               const float* __restrict__ W,
                               const float* __restrict__ bias,
                               float* __restrict__ C,
                               int M, int doRelu) {
    __shared__ float sA[64 * 32];
    __shared__ float sB[32 * 128];
    int tid = threadIdx.x;
    int tr = tid >> 5, tc = tid & 31;
    int brow = blockIdx.x * 64;

    float4 acc[8];
    #pragma unroll
    for (int i = 0; i < 8; i++) acc[i] = make_float4(0.f, 0.f, 0.f, 0.f);

    for (int kb = 0; kb < 4; kb++) {
        // load A tile 64x32
        int lin = tid * 8;
        int ar = lin >> 5, ac = lin & 31;
        int grow = brow + ar;
        float4 z = make_float4(0.f, 0.f, 0.f, 0.f);
        const float* ap = A + (size_t)grow * HID + kb * 32 + ac;
        float4 v0 = (grow < M) ? *(const float4*)ap : z;
        float4 v1 = (grow < M) ? *(const float4*)(ap + 4) : z;
        *(float4*)&sA[lin]     = v0;
        *(float4*)&sA[lin + 4] = v1;
        // load B tile 32x128
        int lb = tid * 16;
        int br = lb >> 7, bc = lb & 127;
        const float* wp = W + (size_t)(kb * 32 + br) * HID + bc;
        *(float4*)&sB[lb]      = *(const float4*)wp;
        *(float4*)&sB[lb + 4]  = *(const float4*)(wp + 4);
        *(float4*)&sB[lb + 8]  = *(const float4*)(wp + 8);
        *(float4*)&sB[lb + 12] = *(const float4*)(wp + 12);
        __syncthreads();

        #pragma unroll 4
        for (int kk = 0; kk < 32; kk++) {
            float4 bv = *(const float4*)&sB[kk * HID + tc * 4];
            #pragma unroll
            for (int i = 0; i < 8; i++) {
                float a = sA[(tr * 8 + i) * 32 + kk];
                acc[i].x = fmaf(a, bv.x, acc[i].x);
                acc[i].y = fmaf(a, bv.y, acc[i].y);
                acc[i].z = fmaf(a, bv.z, acc[i].z);
                acc[i].w = fmaf(a, bv.w, acc[i].w);
            }
        }
        __syncthreads();
    }

    float4 bb = *(const float4*)(bias + tc * 4);
    #pragma unroll
    for (int i = 0; i < 8; i++) {
        int row = brow + tr * 8 + i;
        if (row < M) {
            float4 o;
            o.x = acc[i].x + bb.x;
            o.y = acc[i].y + bb.y;
            o.z = acc[i].z + bb.z;
            o.w = acc[i].w + bb.w;
            if (doRelu) {
                o.x = fmaxf(o.x, 0.f); o.y = fmaxf(o.y, 0.f);
                o.z = fmaxf(o.z, 0.f); o.w = fmaxf(o.w, 0.f);
            }
            *(float4*)&C[(size_t)row * HID + tc * 4] = o;
        }
    }
}

// ---------------------------------------------------------------------------
// Atomic-free mean pool: batch is sorted, binary-search per-graph bounds.
__global__ void pool_kernel(const float* __restrict__ h,
                            const int* __restrict__ batch,
                            float* __restrict__ pool) {
    __shared__ int bounds[2];
    int g = blockIdx.x, t = threadIdx.x;  // 128 threads
    if (t < 2) {
        int target = g + t;
        int lo = 0, hi = NN;
        while (lo < hi) {
            int mid = (lo + hi) >> 1;
            if (batch[mid] < target) lo = mid + 1; else hi = mid;
        }
        bounds[t] = lo;
    }
    __syncthreads();
    int lo = bounds[0], hi = bounds[1];
    float s = 0.f;
    for (int n = lo; n < hi; n++) s += h[(size_t)n * HID + t];
    float cnt = (float)((hi - lo) > 1 ? (hi - lo) : 1);
    pool[g * HID + t] = s / cnt;
}

// ---------------------------------------------------------------------------
// s = relu(g @ fc_w + fc_b); 3 linear heads of width 1.
__global__ void head_kernel(const float* __restrict__ pool,
                            const float* __restrict__ fcw, const float* __restrict__ fcb,
                            const float* __restrict__ hSw, const float* __restrict__ hSb,
                            const float* __restrict__ hPw, const float* __restrict__ hPb,
                            const float* __restrict__ hNw, const float* __restrict__ hNb,
                            float* __restrict__ out) {
    __shared__ float sg[HID];
    __shared__ float red[3][2];
    int g = blockIdx.x, t = threadIdx.x;  // 64 threads
    sg[t]      = pool[g * HID + t];
    sg[t + 64] = pool[g * HID + t + 64];
    __syncthreads();
    float a = fcb[t];
    #pragma unroll 4
    for (int k = 0; k < HID; k++) a = fmaf(sg[k], fcw[k * 64 + t], a);
    float s = fmaxf(a, 0.f);
    float pS = s * hSw[t], pP = s * hPw[t], pN = s * hNw[t];
    #pragma unroll
    for (int off = 16; off; off >>= 1) {
        pS += __shfl_down_sync(0xffffffffu, pS, off);
        pP += __shfl_down_sync(0xffffffffu, pP, off);
        pN += __shfl_down_sync(0xffffffffu, pN, off);
    }
    int warp = t >> 5, lane = t & 31;
    if (lane == 0) { red[0][warp] = pS; red[1][warp] = pP; red[2][warp] = pN; }
    __syncthreads();
    if (t == 0) {
        out[g]            = red[0][0] + red[0][1] + hSb[0];
        out[NG + g]       = red[1][0] + red[1][1] + hPb[0];
        out[2 * NG + g]   = red[2][0] + red[2][1] + hNb[0];
    }
}

// ---------------------------------------------------------------------------
extern "C" void kernel_launch(void* const* d_in, const int* in_sizes, int n_in,
                              void* d_out, int out_size) {
    const float* x     = (const float*)d_in[0];
    const int*   ei    = (const int*)d_in[1];
    const float* eattr = (const float*)d_in[2];
    const int*   batch = (const int*)d_in[3];
    const float *e1w = (const float*)d_in[4],  *e1b = (const float*)d_in[5];
    const float *n1w1 = (const float*)d_in[6], *n1b1 = (const float*)d_in[7];
    const float *n1w2 = (const float*)d_in[8], *n1b2 = (const float*)d_in[9];
    const float *e2w = (const float*)d_in[10], *e2b = (const float*)d_in[11];
    const float *n2w1 = (const float*)d_in[12], *n2b1 = (const float*)d_in[13];
    const float *n2w2 = (const float*)d_in[14], *n2b2 = (const float*)d_in[15];
    const float *fcw = (const float*)d_in[16], *fcb = (const float*)d_in[17];
    const float *hSw = (const float*)d_in[18], *hSb = (const float*)d_in[19];
    const float *hPw = (const float*)d_in[20], *hPb = (const float*)d_in[21];
    const float *hNw = (const float*)d_in[22], *hNb = (const float*)d_in[23];
    float* out = (float*)d_out;

    void *pA, *pB, *pC, *pP;
    cudaGetSymbolAddress(&pA, g_bufA);
    cudaGetSymbolAddress(&pB, g_bufB);
    cudaGetSymbolAddress(&pC, g_bufC);
    cudaGetSymbolAddress(&pP, g_pool);
    float* A = (float*)pA; float* B = (float*)pB;
    float* C = (float*)pC; float* P = (float*)pP;

    const int n4 = NN * HID / 4;
    const int smem_edge = (EIN * HID + 8 * 8 * EIN) * sizeof(float);  // 49152 B
    const int gemm_blocks = (NN + 63) / 64;

    // ----- Layer 1 -----
    copy_kernel<<<4096, 256>>>((const float4*)x, (float4*)A, n4);
    edge_kernel<<<592, 256, smem_edge>>>(x, eattr, ei, e1w, e1b, A);
    gemm128_kernel<<<gemm_blocks, 256>>>(A, n1w1, n1b1, B, NN, 1);
    gemm128_kernel<<<gemm_blocks, 256>>>(B, n1w2, n1b2, C, NN, 1);  // inner + outer relu

    // ----- Layer 2 -----
    copy_kernel<<<4096, 256>>>((const float4*)C, (float4*)A, n4);
    edge_kernel<<<592, 256, smem_edge>>>(C, eattr, ei, e2w, e2b, A);
    gemm128_kernel<<<gemm_blocks, 256>>>(A, n2w1, n2b1, B, NN, 1);
    gemm128_kernel<<<gemm_blocks, 256>>>(B, n2w2, n2b2, C, NN, 1);

    // ----- Pool + heads -----
    pool_kernel<<<NG, HID>>>(C, batch, P);
    head_kernel<<<NG, 64>>>(P, fcw, fcb, hSw, hSb, hPw, hPb, hNw, hNb, out);
}